// round 13
// baseline (speedup 1.0000x reference)
#include <cuda_runtime.h>
#include <cstdint>

#define S 128
#define C 32
#define NN 4096
#define T 512

extern __shared__ char dyn_smem[];

// ---------------- scratch ----------------
__device__ __align__(256) float g_wexp[T * C];    // exp(log_softmax(weights))
__device__ __align__(256) float g_pR[T * C * S];  // p_t, tf32-rounded [T*C, S]
__device__ __align__(256) float g_Pr[S * NN];     // emission probs, tf32-rounded [s][n]
__device__ __align__(256) float g_Tlvl[5][S * S]; // T^(4^k), tf32-rounded
__device__ unsigned g_bcount = 0;                 // grid-barrier counter (self-resetting)
__device__ volatile unsigned g_bsense = 0;        // grid-barrier sense (even flips/run)

// ---------------- helpers ----------------
__device__ __forceinline__ uint32_t smem_u32(const void* p) {
    uint32_t a;
    asm("{ .reg .u64 t; cvta.to.shared.u64 t, %1; cvt.u32.u64 %0, t; }" : "=r"(a) : "l"(p));
    return a;
}
__device__ __forceinline__ void cp_async16(uint32_t dst, const void* src) {
    asm volatile("cp.async.cg.shared.global [%0], [%1], 16;" :: "r"(dst), "l"(src));
}
#define CP_COMMIT() asm volatile("cp.async.commit_group;" ::: "memory")
#define CP_WAIT(n)  asm volatile("cp.async.wait_group %0;" :: "n"(n) : "memory")

__device__ __forceinline__ float to_tf32(float x) {
    uint32_t u;
    asm("cvt.rna.tf32.f32 %0, %1;" : "=r"(u) : "f"(x));
    return __uint_as_float(u);
}
__device__ __forceinline__ void mma_tf32(float* d, const uint32_t* a, const uint32_t* b) {
    asm volatile(
        "mma.sync.aligned.m16n8k8.row.col.f32.tf32.tf32.f32 "
        "{%0,%1,%2,%3},{%4,%5,%6,%7},{%8,%9},{%0,%1,%2,%3};"
        : "+f"(d[0]), "+f"(d[1]), "+f"(d[2]), "+f"(d[3])
        : "r"(a[0]), "r"(a[1]), "r"(a[2]), "r"(a[3]), "r"(b[0]), "r"(b[1]));
}
__device__ __forceinline__ float warpRedMax(float v) {
#pragma unroll
    for (int o = 16; o > 0; o >>= 1) v = fmaxf(v, __shfl_xor_sync(0xffffffffu, v, o));
    return v;
}
__device__ __forceinline__ float warpRedSum(float v) {
#pragma unroll
    for (int o = 16; o > 0; o >>= 1) v += __shfl_xor_sync(0xffffffffu, v, o);
    return v;
}

// ---------------- fused log_softmax over all 4 inputs ----------------
// blocks [0,128): emission -> o4 + g_Pr (tf32, coalesced)
// blocks [128,640): weights -> o5 + g_wexp
// blocks [640,672): init -> o3 (t=0) + g_pR (rounded)
// blocks [672,800): trans -> g_Tlvl[0] (rounded)
__global__ void softmax_all(const float* __restrict__ init, const float* __restrict__ weights,
                            const float* __restrict__ emis, const float* __restrict__ trans,
                            float* __restrict__ o3, float* __restrict__ o4, float* __restrict__ o5) {
    int b = blockIdx.x;
    const float* src;
    float* dlog = nullptr;
    float* dexp = nullptr;
    bool rnd = false;
    int ncols;
    if (b < 128) {
        int row = b;
        src = emis + (size_t)row * NN;  ncols = NN;
        dlog = o4 + (size_t)row * NN;   dexp = g_Pr + (size_t)row * NN;
        rnd = true;
    } else if (b < 640) {
        int row = b - 128;
        src = weights + (size_t)row * C;  ncols = C;
        dlog = o5 + (size_t)row * C;      dexp = g_wexp + (size_t)row * C;
    } else if (b < 672) {
        int row = b - 640;
        src = init + (size_t)row * S;  ncols = S;
        dlog = o3 + (size_t)row * S;   dexp = g_pR + (size_t)row * S;
        rnd = true;
    } else {
        int row = b - 672;
        src = trans + (size_t)row * S;  ncols = S;
        dexp = g_Tlvl[0] + (size_t)row * S;   // T^1
        rnd = true;
    }

    int tid = threadIdx.x, lane = tid & 31, wid = tid >> 5;
    __shared__ float red[8];

    float m = -3.4e38f;
    for (int i = tid; i < ncols; i += blockDim.x) m = fmaxf(m, src[i]);
    m = warpRedMax(m);
    if (lane == 0) red[wid] = m;
    __syncthreads();
    if (wid == 0) {
        float v = (lane < 8) ? red[lane] : -3.4e38f;
        v = warpRedMax(v);
        if (lane == 0) red[0] = v;
    }
    __syncthreads();
    m = red[0];
    __syncthreads();

    float s = 0.f;
    for (int i = tid; i < ncols; i += blockDim.x) s += __expf(src[i] - m);
    s = warpRedSum(s);
    if (lane == 0) red[wid] = s;
    __syncthreads();
    if (wid == 0) {
        float v = (lane < 8) ? red[lane] : 0.f;
        v = warpRedSum(v);
        if (lane == 0) red[0] = v;
    }
    __syncthreads();
    float lse = m + __logf(red[0]);

    for (int i = tid; i < ncols; i += blockDim.x) {
        float v = src[i] - lse;
        if (dlog) dlog[i] = v;
        float e = __expf(v);
        dexp[i] = rnd ? to_tf32(e) : e;
    }
}

// ---------------- single persistent radix-4 doubling kernel (proven) --------
static constexpr int PW = 136;
static constexpr int MAT_W = 128 * PW;
static constexpr int EXP_SMEM = 2 * MAT_W * 4;   // 139264
static constexpr int EXP_GRID = 128;

__global__ __launch_bounds__(256, 1) void expand_fused(float* __restrict__ o3) {
    float* sm0 = reinterpret_cast<float*>(dyn_smem);
    float* Ts = sm0;
    float* W2 = sm0 + MAT_W;
    int tid = threadIdx.x, lane = tid & 31, wid = tid >> 5;
    int bid = blockIdx.x;
    const int G = EXP_GRID;
    unsigned lsense = 0;

#pragma unroll 1
    for (int lvl = 0; lvl < 5; lvl++) {
        int L = 1 << (2 * lvl);
        const float4* gT = reinterpret_cast<const float4*>(g_Tlvl[lvl]);
        for (int i = tid; i < 4096; i += 256) {
            int row = i >> 5, c = i & 31;
            *reinterpret_cast<float4*>(Ts + row * PW + c * 4) = gT[i];
        }
        __syncthreads();

        int nP = min(3 * L, 512 - L);
        int nTask = nP + (lvl < 4 ? 1 : 0);
#pragma unroll 1
        for (int task = bid; task < nTask; task += G) {
            if (task < nP) {
                float* X0 = W2;
                float* X1 = W2 + 32 * PW;
                int t = L + task;
                int m = t / L;
                int j = t - m * L;

                const float4* gp = reinterpret_cast<const float4*>(g_pR + (size_t)j * C * S);
                for (int i = tid; i < 1024; i += 256) {
                    int row = i >> 5, c = i & 31;
                    *reinterpret_cast<float4*>(X0 + row * PW + c * 4) = gp[i];
                }
                __syncthreads();

                int wm = wid & 1, wn = wid >> 1;
                float* srcp = X0;
                float* dstp = X1;
#pragma unroll 1
                for (int it = 0; it < m; it++) {
                    float acc[4][4];
#pragma unroll
                    for (int nt = 0; nt < 4; nt++)
#pragma unroll
                        for (int e = 0; e < 4; e++) acc[nt][e] = 0.f;

#pragma unroll
                    for (int kt = 0; kt < 16; kt++) {
                        int r = wm * 16 + (lane >> 2), k = kt * 8 + (lane & 3);
                        uint32_t a[4];
                        a[0] = __float_as_uint(srcp[r * PW + k]);
                        a[1] = __float_as_uint(srcp[(r + 8) * PW + k]);
                        a[2] = __float_as_uint(srcp[r * PW + k + 4]);
                        a[3] = __float_as_uint(srcp[(r + 8) * PW + k + 4]);
#pragma unroll
                        for (int nt = 0; nt < 4; nt++) {
                            int n = wn * 32 + nt * 8 + (lane >> 2);
                            uint32_t bf[2];
                            bf[0] = __float_as_uint(Ts[k * PW + n]);
                            bf[1] = __float_as_uint(Ts[(k + 4) * PW + n]);
                            mma_tf32(acc[nt], a, bf);
                        }
                    }
                    int r = wm * 16 + (lane >> 2), c2 = (lane & 3) * 2;
#pragma unroll
                    for (int nt = 0; nt < 4; nt++) {
                        int col = wn * 32 + nt * 8 + c2;
                        dstp[r * PW + col]           = to_tf32(acc[nt][0]);
                        dstp[r * PW + col + 1]       = to_tf32(acc[nt][1]);
                        dstp[(r + 8) * PW + col]     = to_tf32(acc[nt][2]);
                        dstp[(r + 8) * PW + col + 1] = to_tf32(acc[nt][3]);
                    }
                    __syncthreads();
                    float* tmp = srcp; srcp = dstp; dstp = tmp;
                }

                float4* gout = reinterpret_cast<float4*>(g_pR + (size_t)t * C * S);
                float* o3out = o3 + (size_t)t * C * S;
                for (int i = tid; i < 1024; i += 256) {
                    int row = i >> 5, c = i & 31;
                    float4 v = *reinterpret_cast<float4*>(srcp + row * PW + c * 4);
                    gout[i] = v;
                    int idx = row * S + c * 4;
                    o3out[idx]     = __logf(v.x);
                    o3out[idx + 1] = __logf(v.y);
                    o3out[idx + 2] = __logf(v.z);
                    o3out[idx + 3] = __logf(v.w);
                }
                __syncthreads();
            } else {
                float* cur = Ts;
                float* dst = W2;
                __syncthreads();
#pragma unroll
                for (int sq = 0; sq < 2; sq++) {
                    float acc[16][4];
#pragma unroll
                    for (int nt = 0; nt < 16; nt++)
#pragma unroll
                        for (int e = 0; e < 4; e++) acc[nt][e] = 0.f;

#pragma unroll
                    for (int kt = 0; kt < 16; kt++) {
                        int r = wid * 16 + (lane >> 2), k = kt * 8 + (lane & 3);
                        uint32_t a[4];
                        a[0] = __float_as_uint(cur[r * PW + k]);
                        a[1] = __float_as_uint(cur[(r + 8) * PW + k]);
                        a[2] = __float_as_uint(cur[r * PW + k + 4]);
                        a[3] = __float_as_uint(cur[(r + 8) * PW + k + 4]);
#pragma unroll
                        for (int nt = 0; nt < 16; nt++) {
                            int n = nt * 8 + (lane >> 2);
                            uint32_t bf[2];
                            bf[0] = __float_as_uint(cur[k * PW + n]);
                            bf[1] = __float_as_uint(cur[(k + 4) * PW + n]);
                            mma_tf32(acc[nt], a, bf);
                        }
                    }
                    __syncthreads();
                    int r = wid * 16 + (lane >> 2), c2 = (lane & 3) * 2;
#pragma unroll
                    for (int nt = 0; nt < 16; nt++) {
                        int col = nt * 8 + c2;
                        dst[r * PW + col]           = to_tf32(acc[nt][0]);
                        dst[r * PW + col + 1]       = to_tf32(acc[nt][1]);
                        dst[(r + 8) * PW + col]     = to_tf32(acc[nt][2]);
                        dst[(r + 8) * PW + col + 1] = to_tf32(acc[nt][3]);
                    }
                    __syncthreads();
                    float* tmp = cur; cur = dst; dst = tmp;
                }
                float4* gout = reinterpret_cast<float4*>(g_Tlvl[lvl + 1]);
                for (int i = tid; i < 4096; i += 256) {
                    int row = i >> 5, c = i & 31;
                    gout[i] = *reinterpret_cast<float4*>(cur + row * PW + c * 4);
                }
            }
        }

        if (lvl < 4) {
            __threadfence();
            __syncthreads();
            if (tid == 0) {
                unsigned ns = lsense ^ 1u;
                unsigned pre = atomicAdd(&g_bcount, 1u);
                if (pre == (unsigned)G - 1u) {
                    atomicExch(&g_bcount, 0u);
                    __threadfence();
                    g_bsense = ns;
                } else {
                    while (g_bsense != ns) { }
                }
            }
            __syncthreads();
            lsense ^= 1u;
        }
    }
}

// ---------------- persistent tf32 GEMM + log epilogue, 512 threads ----------
// grid = 128 CTAs (one t-quad each). A [m=128][k=128] resident; B streamed as
// [k=64][n=128] chunks direct from g_Pr (no transpose). 16 warps:
// warp = (tloc = wid&3, nquarter = wid>>2).
static constexpr int A_PW = 132;                   // A row pitch (words)
static constexpr int A_BYTES = 128 * A_PW * 4;     // 67584
static constexpr int B_NP = 136;                   // B row pitch (words), conflict-free
static constexpr int B_CHUNK = 64 * B_NP * 4;      // 34816
static constexpr int MMA_SMEM = A_BYTES + 3 * B_CHUNK;  // 172032

__global__ __launch_bounds__(512, 1)
void mma_kernel(float* __restrict__ o1, float* __restrict__ o2) {
    char* sm = dyn_smem;
    uint32_t smb = smem_u32(sm);
    int tid = threadIdx.x, lane = tid & 31, wid = tid >> 5;
    int quad = blockIdx.x;

    // prologue: resident A tile
    const uint4* srcA = reinterpret_cast<const uint4*>(g_pR) + (size_t)quad * 128 * 32;
#pragma unroll
    for (int j = 0; j < 8; j++) {
        int i = tid + j * 512;            // 0..4095
        int row = i >> 5, c = i & 31;
        cp_async16(smb + row * (A_PW * 4) + c * 16, srcA + row * 32 + c);
    }
    CP_COMMIT();

    auto issueB = [&](int chunk) {
        int tile = chunk >> 1, half = chunk & 1;
        uint32_t base = smb + A_BYTES + (chunk % 3) * B_CHUNK;
#pragma unroll
        for (int j = 0; j < 4; j++) {
            int i = tid + j * 512;        // 0..2047
            int k = i >> 5, c = i & 31;   // 64 k-rows x 32 16B-chunks
            const uint4* src = reinterpret_cast<const uint4*>(g_Pr)
                               + (size_t)(half * 64 + k) * (NN / 4) + tile * 32 + c;
            cp_async16(base + k * (B_NP * 4) + c * 16, src);
        }
    };
    issueB(0); CP_COMMIT();
    issueB(1); CP_COMMIT();
    issueB(2); CP_COMMIT();

    int tloc = wid & 3, nq = wid >> 2;     // nq 0..3
    int r0 = lane >> 2, cq = lane & 3;
    int t = quad * 4 + tloc;
    float wlane = g_wexp[t * C + lane];
    float wr0  = __shfl_sync(0xffffffffu, wlane, r0);
    float wr0b = __shfl_sync(0xffffffffu, wlane, r0 + 8);
    float wr1  = __shfl_sync(0xffffffffu, wlane, 16 + r0);
    float wr1b = __shfl_sync(0xffffffffu, wlane, 16 + r0 + 8);

    const uint32_t* As = reinterpret_cast<const uint32_t*>(sm);
    float acc[2][4][4];

    for (int chunk = 0; chunk < 64; chunk++) {
        int tile = chunk >> 1, half = chunk & 1;
        CP_WAIT(2);
        __syncthreads();
        const uint32_t* Bs =
            reinterpret_cast<const uint32_t*>(sm + A_BYTES + (chunk % 3) * B_CHUNK);

        if (half == 0) {
#pragma unroll
            for (int mt = 0; mt < 2; mt++)
#pragma unroll
                for (int nt = 0; nt < 4; nt++)
#pragma unroll
                    for (int e = 0; e < 4; e++) acc[mt][nt][e] = 0.f;
        }

#pragma unroll
        for (int step = 0; step < 8; step++) {
            int lk = step * 8 + cq;            // local k in chunk (0..63)
            int k0 = half * 64 + lk;           // global k for A
            uint32_t a[2][4];
#pragma unroll
            for (int mt = 0; mt < 2; mt++) {
                int r = tloc * 32 + mt * 16 + r0;
                a[mt][0] = As[r * A_PW + k0];
                a[mt][1] = As[(r + 8) * A_PW + k0];
                a[mt][2] = As[r * A_PW + k0 + 4];
                a[mt][3] = As[(r + 8) * A_PW + k0 + 4];
            }
#pragma unroll
            for (int nt = 0; nt < 4; nt++) {
                int n = nq * 32 + nt * 8 + r0;
                uint32_t bf[2];
                bf[0] = Bs[lk * B_NP + n];
                bf[1] = Bs[(lk + 4) * B_NP + n];
#pragma unroll
                for (int mt = 0; mt < 2; mt++) mma_tf32(acc[mt][nt], a[mt], bf);
            }
        }
        __syncthreads();
        if (chunk + 3 < 64) issueB(chunk + 3);
        CP_COMMIT();

        if (half == 1) {
            int nb = tile * 128 + nq * 32;
#pragma unroll
            for (int nt = 0; nt < 4; nt++) {
                int ncol = nb + nt * 8 + cq * 2;
                float v0, v1;
                {
                    float2 s0 = make_float2(__logf(acc[0][nt][0]), __logf(acc[0][nt][1]));
                    float2 s1 = make_float2(__logf(acc[0][nt][2]), __logf(acc[0][nt][3]));
                    *reinterpret_cast<float2*>(&o2[((size_t)(t * C + r0)) * NN + ncol]) = s0;
                    *reinterpret_cast<float2*>(&o2[((size_t)(t * C + r0 + 8)) * NN + ncol]) = s1;
                    v0 = acc[0][nt][0] * wr0 + acc[0][nt][2] * wr0b;
                    v1 = acc[0][nt][1] * wr0 + acc[0][nt][3] * wr0b;
                }
                {
                    float2 s0 = make_float2(__logf(acc[1][nt][0]), __logf(acc[1][nt][1]));
                    float2 s1 = make_float2(__logf(acc[1][nt][2]), __logf(acc[1][nt][3]));
                    *reinterpret_cast<float2*>(&o2[((size_t)(t * C + 16 + r0)) * NN + ncol]) = s0;
                    *reinterpret_cast<float2*>(&o2[((size_t)(t * C + 24 + r0)) * NN + ncol]) = s1;
                    v0 += acc[1][nt][0] * wr1 + acc[1][nt][2] * wr1b;
                    v1 += acc[1][nt][1] * wr1 + acc[1][nt][3] * wr1b;
                }
#pragma unroll
                for (int o = 4; o < 32; o <<= 1) {
                    v0 += __shfl_xor_sync(0xffffffffu, v0, o);
                    v1 += __shfl_xor_sync(0xffffffffu, v1, o);
                }
                if (lane < 4) {
                    int n = nb + nt * 8 + lane * 2;
                    *reinterpret_cast<float2*>(&o1[(size_t)t * NN + n]) =
                        make_float2(__logf(v0), __logf(v1));
                }
            }
        }
    }
}

// ---------------- launch ----------------
extern "C" void kernel_launch(void* const* d_in, const int* in_sizes, int n_in,
                              void* d_out, int out_size) {
    (void)in_sizes; (void)n_in; (void)out_size;
    const float* init    = (const float*)d_in[0];   // [32,128]
    const float* weights = (const float*)d_in[1];   // [512,32]
    const float* emis    = (const float*)d_in[2];   // [128,4096]
    const float* trans   = (const float*)d_in[3];   // [128,128]

    float* out = (float*)d_out;
    float* o1 = out;                       // [512,4096]
    float* o2 = o1 + (size_t)T * NN;       // [512,32,4096]
    float* o3 = o2 + (size_t)T * C * NN;   // [512,32,128]
    float* o4 = o3 + (size_t)T * C * S;    // [128,4096]
    float* o5 = o4 + (size_t)S * NN;       // [512,32]

    cudaFuncSetAttribute(expand_fused, cudaFuncAttributeMaxDynamicSharedMemorySize, EXP_SMEM);
    cudaFuncSetAttribute(mma_kernel, cudaFuncAttributeMaxDynamicSharedMemorySize, MMA_SMEM);

    // 1) fused softmax over all inputs (emission probs now stored K-major tf32)
    softmax_all<<<800, 256>>>(init, weights, emis, trans, o3, o4, o5);

    // 2) all 5 doubling levels in ONE persistent kernel (grid barriers inside)
    expand_fused<<<EXP_GRID, 256, EXP_SMEM>>>(o3);

    // 3) persistent tf32 GEMM + log epilogue, 512 threads (outputs 1, 2)
    mma_kernel<<<128, 512, MMA_SMEM>>>(o1, o2);
}

// round 15
// speedup vs baseline: 1.0374x; 1.0374x over previous
#include <cuda_runtime.h>
#include <cstdint>

#define S 128
#define C 32
#define NN 4096
#define T 512

extern __shared__ char dyn_smem[];

// ---------------- scratch ----------------
__device__ __align__(256) float g_wexp[T * C];    // exp(log_softmax(weights))
__device__ __align__(256) float g_pR[T * C * S];  // p_t, tf32-rounded [T*C, S]
__device__ __align__(256) float g_Pr[S * NN];     // emission probs, tf32-rounded [s][n]
__device__ __align__(256) float g_Tlvl[5][S * S]; // T^(4^k), tf32-rounded
__device__ __align__(256) float g_Tsq[S * S];     // squaring intermediate T^(2L)
__device__ unsigned g_bcount = 0;                 // grid-barrier counter (self-resetting)
__device__ volatile unsigned g_bsense = 0;        // grid-barrier sense (even flips/run)

// ---------------- helpers ----------------
__device__ __forceinline__ uint32_t smem_u32(const void* p) {
    uint32_t a;
    asm("{ .reg .u64 t; cvta.to.shared.u64 t, %1; cvt.u32.u64 %0, t; }" : "=r"(a) : "l"(p));
    return a;
}
__device__ __forceinline__ void cp_async16(uint32_t dst, const void* src) {
    asm volatile("cp.async.cg.shared.global [%0], [%1], 16;" :: "r"(dst), "l"(src));
}
#define CP_COMMIT() asm volatile("cp.async.commit_group;" ::: "memory")
#define CP_WAIT(n)  asm volatile("cp.async.wait_group %0;" :: "n"(n) : "memory")

__device__ __forceinline__ float to_tf32(float x) {
    uint32_t u;
    asm("cvt.rna.tf32.f32 %0, %1;" : "=r"(u) : "f"(x));
    return __uint_as_float(u);
}
__device__ __forceinline__ void mma_tf32(float* d, const uint32_t* a, const uint32_t* b) {
    asm volatile(
        "mma.sync.aligned.m16n8k8.row.col.f32.tf32.tf32.f32 "
        "{%0,%1,%2,%3},{%4,%5,%6,%7},{%8,%9},{%0,%1,%2,%3};"
        : "+f"(d[0]), "+f"(d[1]), "+f"(d[2]), "+f"(d[3])
        : "r"(a[0]), "r"(a[1]), "r"(a[2]), "r"(a[3]), "r"(b[0]), "r"(b[1]));
}
__device__ __forceinline__ float warpRedMax(float v) {
#pragma unroll
    for (int o = 16; o > 0; o >>= 1) v = fmaxf(v, __shfl_xor_sync(0xffffffffu, v, o));
    return v;
}
__device__ __forceinline__ float warpRedSum(float v) {
#pragma unroll
    for (int o = 16; o > 0; o >>= 1) v += __shfl_xor_sync(0xffffffffu, v, o);
    return v;
}

// ---------------- fused log_softmax over all 4 inputs ----------------
__global__ void softmax_all(const float* __restrict__ init, const float* __restrict__ weights,
                            const float* __restrict__ emis, const float* __restrict__ trans,
                            float* __restrict__ o3, float* __restrict__ o4, float* __restrict__ o5) {
    int b = blockIdx.x;
    const float* src;
    float* dlog = nullptr;
    float* dexp = nullptr;
    bool rnd = false;
    int ncols;
    if (b < 128) {
        int row = b;
        src = emis + (size_t)row * NN;  ncols = NN;
        dlog = o4 + (size_t)row * NN;   dexp = g_Pr + (size_t)row * NN;
        rnd = true;
    } else if (b < 640) {
        int row = b - 128;
        src = weights + (size_t)row * C;  ncols = C;
        dlog = o5 + (size_t)row * C;      dexp = g_wexp + (size_t)row * C;
    } else if (b < 672) {
        int row = b - 640;
        src = init + (size_t)row * S;  ncols = S;
        dlog = o3 + (size_t)row * S;   dexp = g_pR + (size_t)row * S;
        rnd = true;
    } else {
        int row = b - 672;
        src = trans + (size_t)row * S;  ncols = S;
        dexp = g_Tlvl[0] + (size_t)row * S;   // T^1
        rnd = true;
    }

    int tid = threadIdx.x, lane = tid & 31, wid = tid >> 5;
    __shared__ float red[8];

    float m = -3.4e38f;
    for (int i = tid; i < ncols; i += blockDim.x) m = fmaxf(m, src[i]);
    m = warpRedMax(m);
    if (lane == 0) red[wid] = m;
    __syncthreads();
    if (wid == 0) {
        float v = (lane < 8) ? red[lane] : -3.4e38f;
        v = warpRedMax(v);
        if (lane == 0) red[0] = v;
    }
    __syncthreads();
    m = red[0];
    __syncthreads();

    float s = 0.f;
    for (int i = tid; i < ncols; i += blockDim.x) s += __expf(src[i] - m);
    s = warpRedSum(s);
    if (lane == 0) red[wid] = s;
    __syncthreads();
    if (wid == 0) {
        float v = (lane < 8) ? red[lane] : 0.f;
        v = warpRedSum(v);
        if (lane == 0) red[0] = v;
    }
    __syncthreads();
    float lse = m + __logf(red[0]);

    for (int i = tid; i < ncols; i += blockDim.x) {
        float v = src[i] - lse;
        if (dlog) dlog[i] = v;
        float e = __expf(v);
        dexp[i] = rnd ? to_tf32(e) : e;
    }
}

// ---------------- persistent radix-4 doubling, squaring split 8-way --------
static constexpr int PW = 136;
static constexpr int MAT_W = 128 * PW;
static constexpr int EXP_SMEM = 2 * MAT_W * 4;   // 139264
static constexpr int EXP_GRID = 128;

__device__ __forceinline__ void grid_barrier(unsigned& lsense, int tid) {
    __threadfence();
    __syncthreads();
    if (tid == 0) {
        unsigned ns = lsense ^ 1u;
        unsigned pre = atomicAdd(&g_bcount, 1u);
        if (pre == (unsigned)EXP_GRID - 1u) {
            atomicExch(&g_bcount, 0u);
            __threadfence();
            g_bsense = ns;
        } else {
            while (g_bsense != ns) { }
        }
    }
    __syncthreads();
    lsense ^= 1u;
}

// compute 16 rows [sqb*16, +16) of X*X (X in smem, pitch PW) -> gdst (row-major S, tf32)
__device__ __forceinline__ void square16(const float* X, float* gdst, int sqb,
                                         int wid, int lane) {
    int rbase = sqb * 16;
    float acc[2][4];
#pragma unroll
    for (int nt = 0; nt < 2; nt++)
#pragma unroll
        for (int e = 0; e < 4; e++) acc[nt][e] = 0.f;

#pragma unroll
    for (int kt = 0; kt < 16; kt++) {
        int r = rbase + (lane >> 2), k = kt * 8 + (lane & 3);
        uint32_t a[4];
        a[0] = __float_as_uint(X[r * PW + k]);
        a[1] = __float_as_uint(X[(r + 8) * PW + k]);
        a[2] = __float_as_uint(X[r * PW + k + 4]);
        a[3] = __float_as_uint(X[(r + 8) * PW + k + 4]);
#pragma unroll
        for (int nt = 0; nt < 2; nt++) {
            int n = wid * 16 + nt * 8 + (lane >> 2);
            uint32_t bf[2];
            bf[0] = __float_as_uint(X[k * PW + n]);
            bf[1] = __float_as_uint(X[(k + 4) * PW + n]);
            mma_tf32(acc[nt], a, bf);
        }
    }
    int r = rbase + (lane >> 2), c2 = (lane & 3) * 2;
#pragma unroll
    for (int nt = 0; nt < 2; nt++) {
        int col = wid * 16 + nt * 8 + c2;
        gdst[r * S + col]           = to_tf32(acc[nt][0]);
        gdst[r * S + col + 1]       = to_tf32(acc[nt][1]);
        gdst[(r + 8) * S + col]     = to_tf32(acc[nt][2]);
        gdst[(r + 8) * S + col + 1] = to_tf32(acc[nt][3]);
    }
}

__global__ __launch_bounds__(256, 1) void expand_fused(float* __restrict__ o3) {
    float* sm0 = reinterpret_cast<float*>(dyn_smem);
    float* Ts = sm0;
    float* W2 = sm0 + MAT_W;
    int tid = threadIdx.x, lane = tid & 31, wid = tid >> 5;
    int bid = blockIdx.x;
    const int G = EXP_GRID;
    unsigned lsense = 0;

#pragma unroll 1
    for (int lvl = 0; lvl < 5; lvl++) {
        int L = 1 << (2 * lvl);
        const float4* gT = reinterpret_cast<const float4*>(g_Tlvl[lvl]);
        for (int i = tid; i < 4096; i += 256) {
            int row = i >> 5, c = i & 31;
            *reinterpret_cast<float4*>(Ts + row * PW + c * 4) = gT[i];
        }
        __syncthreads();

        int nP = min(3 * L, 512 - L);
#pragma unroll 1
        for (int task = bid; task < nP; task += G) {
            float* X0 = W2;
            float* X1 = W2 + 32 * PW;
            int t = L + task;
            int m = t / L;
            int j = t - m * L;

            const float4* gp = reinterpret_cast<const float4*>(g_pR + (size_t)j * C * S);
            for (int i = tid; i < 1024; i += 256) {
                int row = i >> 5, c = i & 31;
                *reinterpret_cast<float4*>(X0 + row * PW + c * 4) = gp[i];
            }
            __syncthreads();

            int wm = wid & 1, wn = wid >> 1;
            float* srcp = X0;
            float* dstp = X1;
#pragma unroll 1
            for (int it = 0; it < m; it++) {
                float acc[4][4];
#pragma unroll
                for (int nt = 0; nt < 4; nt++)
#pragma unroll
                    for (int e = 0; e < 4; e++) acc[nt][e] = 0.f;

#pragma unroll
                for (int kt = 0; kt < 16; kt++) {
                    int r = wm * 16 + (lane >> 2), k = kt * 8 + (lane & 3);
                    uint32_t a[4];
                    a[0] = __float_as_uint(srcp[r * PW + k]);
                    a[1] = __float_as_uint(srcp[(r + 8) * PW + k]);
                    a[2] = __float_as_uint(srcp[r * PW + k + 4]);
                    a[3] = __float_as_uint(srcp[(r + 8) * PW + k + 4]);
#pragma unroll
                    for (int nt = 0; nt < 4; nt++) {
                        int n = wn * 32 + nt * 8 + (lane >> 2);
                        uint32_t bf[2];
                        bf[0] = __float_as_uint(Ts[k * PW + n]);
                        bf[1] = __float_as_uint(Ts[(k + 4) * PW + n]);
                        mma_tf32(acc[nt], a, bf);
                    }
                }
                int r = wm * 16 + (lane >> 2), c2 = (lane & 3) * 2;
#pragma unroll
                for (int nt = 0; nt < 4; nt++) {
                    int col = wn * 32 + nt * 8 + c2;
                    dstp[r * PW + col]           = to_tf32(acc[nt][0]);
                    dstp[r * PW + col + 1]       = to_tf32(acc[nt][1]);
                    dstp[(r + 8) * PW + col]     = to_tf32(acc[nt][2]);
                    dstp[(r + 8) * PW + col + 1] = to_tf32(acc[nt][3]);
                }
                __syncthreads();
                float* tmp = srcp; srcp = dstp; dstp = tmp;
            }

            float4* gout = reinterpret_cast<float4*>(g_pR + (size_t)t * C * S);
            float* o3out = o3 + (size_t)t * C * S;
            for (int i = tid; i < 1024; i += 256) {
                int row = i >> 5, c = i & 31;
                float4 v = *reinterpret_cast<float4*>(srcp + row * PW + c * 4);
                gout[i] = v;
                int idx = row * S + c * 4;
                o3out[idx]     = __logf(v.x);
                o3out[idx + 1] = __logf(v.y);
                o3out[idx + 2] = __logf(v.z);
                o3out[idx + 3] = __logf(v.w);
            }
            __syncthreads();
        }

        if (lvl < 4) {
            // phase A: T^{2L} = T^L * T^L, 8 CTAs x 16 rows
            if (bid >= G - 8) {
                square16(Ts, g_Tsq, bid - (G - 8), wid, lane);
            }
            grid_barrier(lsense, tid);
            // phase B: T^{4L} = T^{2L} * T^{2L}
            if (bid >= G - 8) {
                const float4* gS = reinterpret_cast<const float4*>(g_Tsq);
                for (int i = tid; i < 4096; i += 256) {
                    int row = i >> 5, c = i & 31;
                    *reinterpret_cast<float4*>(W2 + row * PW + c * 4) = gS[i];
                }
                __syncthreads();
                square16(W2, g_Tlvl[lvl + 1], bid - (G - 8), wid, lane);
            }
            grid_barrier(lsense, tid);
        }
    }
}

// ---------------- persistent tf32 GEMM + log epilogue, 256 threads ----------
// grid = 128 CTAs (one t-quad each). A [m=128][k=128] resident; B streamed as
// [k=64][n=128] chunks direct from g_Pr. 8 warps: warp = (tloc=wid&3, nhalf=wid>>2).
static constexpr int A_PW = 132;
static constexpr int A_BYTES = 128 * A_PW * 4;     // 67584
static constexpr int B_NP = 136;                   // B chunk row pitch (words)
static constexpr int B_CHUNK = 64 * B_NP * 4;      // 34816
static constexpr int MMA_SMEM = A_BYTES + 3 * B_CHUNK;  // 172032

__global__ __launch_bounds__(256, 1)
void mma_kernel(float* __restrict__ o1, float* __restrict__ o2) {
    char* sm = dyn_smem;
    uint32_t smb = smem_u32(sm);
    int tid = threadIdx.x, lane = tid & 31, wid = tid >> 5;
    int quad = blockIdx.x;

    const uint4* srcA = reinterpret_cast<const uint4*>(g_pR) + (size_t)quad * 128 * 32;
#pragma unroll
    for (int j = 0; j < 16; j++) {
        int i = tid + j * 256;
        int row = i >> 5, c = i & 31;
        cp_async16(smb + row * (A_PW * 4) + c * 16, srcA + row * 32 + c);
    }
    CP_COMMIT();

    auto issueB = [&](int chunk) {
        int tile = chunk >> 1, half = chunk & 1;
        uint32_t base = smb + A_BYTES + (chunk % 3) * B_CHUNK;
#pragma unroll
        for (int j = 0; j < 8; j++) {
            int i = tid + j * 256;        // 0..2047
            int k = i >> 5, c = i & 31;   // 64 k-rows x 32 16B-chunks
            const uint4* src = reinterpret_cast<const uint4*>(g_Pr)
                               + (size_t)(half * 64 + k) * (NN / 4) + tile * 32 + c;
            cp_async16(base + k * (B_NP * 4) + c * 16, src);
        }
    };
    issueB(0); CP_COMMIT();
    issueB(1); CP_COMMIT();
    issueB(2); CP_COMMIT();

    int mrow = (wid & 3) * 32 + (lane >> 2);
    int nrowBase = (wid >> 2) * 64 + (lane >> 2);
    int kt = lane & 3;
    int t = quad * 4 + (wid & 3);
    int r0 = lane >> 2, cq = lane & 3;
    float wlane = g_wexp[t * C + lane];
    float wr0  = __shfl_sync(0xffffffffu, wlane, r0);
    float wr0b = __shfl_sync(0xffffffffu, wlane, r0 + 8);
    float wr1  = __shfl_sync(0xffffffffu, wlane, 16 + r0);
    float wr1b = __shfl_sync(0xffffffffu, wlane, 16 + r0 + 8);

    const uint32_t* As = reinterpret_cast<const uint32_t*>(sm);
    float acc[2][8][4];

    for (int chunk = 0; chunk < 64; chunk++) {
        int tile = chunk >> 1, half = chunk & 1;
        CP_WAIT(2);
        __syncthreads();
        const uint32_t* Bs =
            reinterpret_cast<const uint32_t*>(sm + A_BYTES + (chunk % 3) * B_CHUNK);

        if (half == 0) {
#pragma unroll
            for (int mt = 0; mt < 2; mt++)
#pragma unroll
                for (int nt = 0; nt < 8; nt++)
#pragma unroll
                    for (int e = 0; e < 4; e++) acc[mt][nt][e] = 0.f;
        }

#pragma unroll
        for (int step = 0; step < 8; step++) {
            int lk = step * 8 + kt;            // local k in chunk
            int k0 = half * 64 + lk;           // global k for A
            uint32_t a[2][4];
#pragma unroll
            for (int mt = 0; mt < 2; mt++) {
                int r = mrow + mt * 16;
                a[mt][0] = As[r * A_PW + k0];
                a[mt][1] = As[(r + 8) * A_PW + k0];
                a[mt][2] = As[r * A_PW + k0 + 4];
                a[mt][3] = As[(r + 8) * A_PW + k0 + 4];
            }
#pragma unroll
            for (int nt = 0; nt < 8; nt++) {
                int n = nrowBase + nt * 8;
                uint32_t bf[2];
                bf[0] = Bs[lk * B_NP + n];
                bf[1] = Bs[(lk + 4) * B_NP + n];
#pragma unroll
                for (int mt = 0; mt < 2; mt++) mma_tf32(acc[mt][nt], a[mt], bf);
            }
        }
        __syncthreads();
        if (chunk + 3 < 64) issueB(chunk + 3);
        CP_COMMIT();

        if (half == 1) {
            int nb = tile * 128;
            int nbL = (wid >> 2) * 64;
#pragma unroll
            for (int nt = 0; nt < 8; nt++) {
                int ncol = nb + nbL + nt * 8 + cq * 2;
                float v0, v1;
                {
                    float2 s0 = make_float2(__logf(acc[0][nt][0]), __logf(acc[0][nt][1]));
                    float2 s1 = make_float2(__logf(acc[0][nt][2]), __logf(acc[0][nt][3]));
                    *reinterpret_cast<float2*>(&o2[((size_t)(t * C + r0)) * NN + ncol]) = s0;
                    *reinterpret_cast<float2*>(&o2[((size_t)(t * C + r0 + 8)) * NN + ncol]) = s1;
                    v0 = acc[0][nt][0] * wr0 + acc[0][nt][2] * wr0b;
                    v1 = acc[0][nt][1] * wr0 + acc[0][nt][3] * wr0b;
                }
                {
                    float2 s0 = make_float2(__logf(acc[1][nt][0]), __logf(acc[1][nt][1]));
                    float2 s1 = make_float2(__logf(acc[1][nt][2]), __logf(acc[1][nt][3]));
                    *reinterpret_cast<float2*>(&o2[((size_t)(t * C + 16 + r0)) * NN + ncol]) = s0;
                    *reinterpret_cast<float2*>(&o2[((size_t)(t * C + 24 + r0)) * NN + ncol]) = s1;
                    v0 += acc[1][nt][0] * wr1 + acc[1][nt][2] * wr1b;
                    v1 += acc[1][nt][1] * wr1 + acc[1][nt][3] * wr1b;
                }
#pragma unroll
                for (int o = 4; o < 32; o <<= 1) {
                    v0 += __shfl_xor_sync(0xffffffffu, v0, o);
                    v1 += __shfl_xor_sync(0xffffffffu, v1, o);
                }
                if (lane < 4) {
                    int n = nb + nbL + nt * 8 + lane * 2;
                    *reinterpret_cast<float2*>(&o1[(size_t)t * NN + n]) =
                        make_float2(__logf(v0), __logf(v1));
                }
            }
        }
    }
}

// ---------------- launch ----------------
extern "C" void kernel_launch(void* const* d_in, const int* in_sizes, int n_in,
                              void* d_out, int out_size) {
    (void)in_sizes; (void)n_in; (void)out_size;
    const float* init    = (const float*)d_in[0];   // [32,128]
    const float* weights = (const float*)d_in[1];   // [512,32]
    const float* emis    = (const float*)d_in[2];   // [128,4096]
    const float* trans   = (const float*)d_in[3];   // [128,128]

    float* out = (float*)d_out;
    float* o1 = out;                       // [512,4096]
    float* o2 = o1 + (size_t)T * NN;       // [512,32,4096]
    float* o3 = o2 + (size_t)T * C * NN;   // [512,32,128]
    float* o4 = o3 + (size_t)T * C * S;    // [128,4096]
    float* o5 = o4 + (size_t)S * NN;       // [512,32]

    cudaFuncSetAttribute(expand_fused, cudaFuncAttributeMaxDynamicSharedMemorySize, EXP_SMEM);
    cudaFuncSetAttribute(mma_kernel, cudaFuncAttributeMaxDynamicSharedMemorySize, MMA_SMEM);

    // 1) fused softmax over all inputs
    softmax_all<<<800, 256>>>(init, weights, emis, trans, o3, o4, o5);

    // 2) all 5 doubling levels in ONE persistent kernel (squaring split 8-way)
    expand_fused<<<EXP_GRID, 256, EXP_SMEM>>>(o3);

    // 3) persistent tf32 GEMM + log epilogue, 256 threads (outputs 1, 2)
    mma_kernel<<<128, 256, MMA_SMEM>>>(o1, o2);
}